// round 16
// baseline (speedup 1.0000x reference)
#include <cuda_runtime.h>
#include <math.h>

#define NB      32
#define T_IN    512
#define NEW_T   426
#define NCC     1629            // N*C = 543*3
#define JF      53              // JITTER_FREQ
#define X_ELEMS (NB*NEW_T*NCC)  // 22,205,088
#define BTHREADS 416            // 416*4 = 1664 >= 1629
#define RROWS   6               // 426 = 71 * 6
#define XBLOCKS (NEW_T / RROWS) // 71

// Per-(b,t) table: x = idx0 (or -1.0f if frame kept), y = idx1, z = drop-interp frac, w = jitter
__device__ float4 g_tab[NB * NEW_T];
__device__ int    g_flag[NB];   // set when g_tab rows for b are ready; reset by last block
__device__ int    g_done[NB];   // completion counter per b

__device__ __forceinline__ int read_bool(const void* p, int mode, int i) {
    if (mode == 0) return ((const unsigned char*)p)[i] != 0;
    if (mode == 1) return ((const int*)p)[i] != 0;
    return ((const float*)p)[i] != 0.0f;
}

__device__ __forceinline__ int probe_mode(const void* p, int known_true_idx) {
    if (((const unsigned char*)p)[known_true_idx] != 0) return 0;   // u8
    if (((const int*)p)[known_true_idx] == 1) return 1;             // i32
    return 2;                                                       // f32
}

__device__ __forceinline__ void ridx(int tt, int& i0, float& f) {
    float s = (float)tt * (float)(511.0 / 425.0);
    int i = (int)s;
    if (i > T_IN - 2) i = T_IN - 2;
    i0 = i;
    f = s - (float)i;
}

// Compact row metadata: 32-bit element offsets into xb.
struct RowMeta {
    unsigned o0, o1;
    float f0, w0, f1, w1;
    float jit;
    int two;
};

__device__ __forceinline__ RowMeta mkmeta(const float4& tb, int tt, bool zero_jit)
{
    RowMeta m;
    int i0; float f;
    if (tb.x < 0.0f) {
        ridx(tt, i0, f);
        m.o0 = (unsigned)i0 * NCC; m.f0 = f; m.w0 = 1.0f;
        m.two = 0; m.o1 = m.o0; m.f1 = 0.f; m.w1 = 0.f;
    } else {
        ridx((int)tb.x, i0, f);
        m.o0 = (unsigned)i0 * NCC; m.f0 = f; m.w0 = 1.0f - tb.z;
        int i1; float f1; ridx((int)tb.y, i1, f1);
        m.o1 = (unsigned)i1 * NCC; m.f1 = f1; m.w1 = tb.z;
        m.two = 1;
    }
    m.jit = zero_jit ? 0.0f : tb.w;
    return m;
}

__device__ __forceinline__ void issue_arm0(const float* __restrict__ xb, const RowMeta& m,
                                           int tid, float* v0, float* v1)
{
    const float* p = xb + m.o0 + tid;
    #pragma unroll
    for (int k = 0; k < 4; k++) if (tid + k * BTHREADS < NCC) v0[k] = __ldg(p + k * BTHREADS);
    #pragma unroll
    for (int k = 0; k < 4; k++) if (tid + k * BTHREADS < NCC) v1[k] = __ldg(p + NCC + k * BTHREADS);
}

__device__ __forceinline__ void combine(const float* __restrict__ xb, const RowMeta& m,
                                        int tid, const float* v0, const float* v1, float* cur)
{
    #pragma unroll
    for (int k = 0; k < 4; k++)
        cur[k] = m.w0 * (v0[k] * (1.0f - m.f0) + v1[k] * m.f0);
    if (m.two) {                               // block-uniform, rare (~10% rows)
        const float* p = xb + m.o1 + tid;
        float u0[4], u1[4];
        #pragma unroll
        for (int k = 0; k < 4; k++) if (tid + k * BTHREADS < NCC) u0[k] = __ldg(p + k * BTHREADS);
        #pragma unroll
        for (int k = 0; k < 4; k++) if (tid + k * BTHREADS < NCC) u1[k] = __ldg(p + NCC + k * BTHREADS);
        #pragma unroll
        for (int k = 0; k < 4; k++)
            cur[k] += m.w1 * (u0[k] * (1.0f - m.f1) + u1[k] * m.f1);
    }
}

// Single fused kernel. Block x==0 of each b builds g_tab[b] and releases a flag;
// the other 70 blocks of b spin on it (overlapped with their independent loads).
// Last finisher per b resets flag+counter so the kernel is replay-deterministic.
__global__ void __launch_bounds__(BTHREADS, 3)
fused_kernel(const float* __restrict__ x, const float* __restrict__ noise,
             const float* __restrict__ sp, const void* __restrict__ mask,
             const void* __restrict__ keep, const float* __restrict__ bj,
             float* __restrict__ out, int write_mask)
{
    __shared__ unsigned char s_kv[NEW_T];
    __shared__ short         s_kept[NEW_T];
    __shared__ int           s_K;

    const int t0 = blockIdx.x * RROWS;
    const int b  = blockIdx.y;
    const int row0 = b * NEW_T + t0;
    const int tid = threadIdx.x;

    const float* __restrict__ xb = x + (size_t)b * T_IN * NCC;

    // --- g_tab-independent loads first (overlap with setup / spin) ---
    const float* spp = sp + (size_t)b * NCC + tid;
    float spv[4];
    #pragma unroll
    for (int k = 0; k < 4; k++) if (tid + k * BTHREADS < NCC) spv[k] = __ldg(spp + k * BTHREADS);

    float nz[4];
    {
        const float* np = noise + (size_t)row0 * NCC + tid;
        #pragma unroll
        for (int k = 0; k < 4; k++) if (tid + k * BTHREADS < NCC) nz[k] = __ldcs(np + k * BTHREADS);
    }

    if (blockIdx.x == 0) {
        // ================= setup for batch row b =================
        const int bmode = probe_mode(keep, NEW_T - 1);

        // keep bits -> shared (coalesced)
        if (tid < NEW_T)       s_kv[tid]       = (unsigned char)read_bool(keep, bmode, b * NEW_T + tid);
        if (tid < NEW_T - BTHREADS) s_kv[tid + BTHREADS] =
            (unsigned char)read_bool(keep, bmode, b * NEW_T + tid + BTHREADS);
        __syncthreads();

        // warp 0: scan 426 bits, 14 per lane
        if (tid < 32) {
            const int lane = tid;
            int cnt = 0;
            #pragma unroll
            for (int j = 0; j < 14; j++) {
                int t = lane * 14 + j;
                if (t < NEW_T) cnt += s_kv[t];
            }
            // exclusive warp scan of cnt
            int excl = cnt;
            #pragma unroll
            for (int off = 1; off < 32; off <<= 1) {
                int n = __shfl_up_sync(0xffffffffu, excl, off);
                if (lane >= off) excl += n;
            }
            excl -= cnt;   // exclusive
            int pos = excl;
            #pragma unroll
            for (int j = 0; j < 14; j++) {
                int t = lane * 14 + j;
                if (t < NEW_T && s_kv[t]) s_kept[pos++] = (short)t;
            }
            if (lane == 31) s_K = excl + cnt;
        }
        __syncthreads();
        const int K = s_K;

        // build g_tab rows (two passes: t=tid, t=tid+416)
        #pragma unroll
        for (int pass = 0; pass < 2; pass++) {
            const int t = tid + pass * BTHREADS;
            if (t < NEW_T) {
                const int kvt = s_kv[t];
                float s  = (float)t * (float)(K - 1) / 425.0f;
                int  r0  = (int)floorf(s);
                if (r0 < 0) r0 = 0;
                if (r0 > K - 2) r0 = K - 2;
                float fr = s - (float)r0;

                float4 tb;
                if (kvt) { tb.x = -1.0f; tb.y = 0.0f; tb.z = 0.0f; }
                else     { tb.x = (float)s_kept[r0]; tb.y = (float)s_kept[r0 + 1]; tb.z = fr; }

                float sj = (float)t * (float)(52.0 / 425.0);
                int  j0  = (int)floorf(sj);
                if (j0 > JF - 2) j0 = JF - 2;
                float fj = sj - (float)j0;
                tb.w = (bj[b * JF + j0] * 0.02f) * (1.0f - fj) + (bj[b * JF + j0 + 1] * 0.02f) * fj;

                g_tab[b * NEW_T + t] = tb;

                if (write_mask) {
                    float nf = (float)t * (float)(512.0 / 426.0);
                    int ni = (int)floorf(nf);
                    if (ni > T_IN - 1) ni = T_IN - 1;
                    int m = read_bool(mask, bmode, b * T_IN + ni);
                    out[X_ELEMS + b * NEW_T + t] = (m && kvt) ? 1.0f : 0.0f;
                }
            }
        }
        __syncthreads();
        if (tid == 0) {
            __threadfence();                        // release g_tab writes
            ((volatile int*)g_flag)[b] = 1;
        }
        // setup block reads back its own g_tab rows below (L2-hot, coherent)
    } else {
        // ================= wait for setup of batch b =================
        if (tid == 0) {
            while (((volatile int*)g_flag)[b] == 0) { __nanosleep(64); }
            __threadfence();                        // acquire before g_tab reads
        }
        __syncthreads();
    }

    // ================= main strip (R13 structure, 1-deep pipeline) =================
    float prev[4] = {0.f, 0.f, 0.f, 0.f};
    if (t0 > 0) {
        RowMeta mp = mkmeta(g_tab[row0 - 1], t0 - 1, false);
        float pv0[4], pv1[4];
        issue_arm0(xb, mp, tid, pv0, pv1);
        combine(xb, mp, tid, pv0, pv1, prev);
    }

    RowMeta mc = mkmeta(g_tab[row0], t0, t0 == 0);
    float va0[4], va1[4];
    issue_arm0(xb, mc, tid, va0, va1);

    #pragma unroll
    for (int i = 0; i < RROWS; i++) {
        const int row = row0 + i;

        RowMeta mn;
        float vb0[4], vb1[4], nz2[4];
        if (i + 1 < RROWS) {
            mn = mkmeta(g_tab[row + 1], t0 + i + 1, false);
            issue_arm0(xb, mn, tid, vb0, vb1);
            const float* np = noise + (size_t)(row + 1) * NCC + tid;
            #pragma unroll
            for (int k = 0; k < 4; k++) if (tid + k * BTHREADS < NCC) nz2[k] = __ldcs(np + k * BTHREADS);
        }

        float cur[4];
        combine(xb, mc, tid, va0, va1, cur);

        float* op = out + (size_t)row * NCC + tid;
        const float jit = mc.jit;
        #pragma unroll
        for (int k = 0; k < 4; k++) {
            if (tid + k * BTHREADS < NCC) {
                float v = cur[k] + (cur[k] - prev[k]) * jit;   // jit==0 at t==0
                __stcs(op + k * BTHREADS, v + nz[k] * 0.01f + spv[k] * 0.005f);
            }
        }

        #pragma unroll
        for (int k = 0; k < 4; k++) { prev[k] = cur[k]; va0[k] = vb0[k]; va1[k] = vb1[k]; nz[k] = nz2[k]; }
        mc = mn;
    }

    // ================= replay-safe reset =================
    __syncthreads();
    if (tid == 0) {
        int old = atomicAdd(&g_done[b], 1);
        if (old == XBLOCKS - 1) {                   // last block of this b
            g_done[b] = 0;
            __threadfence();
            ((volatile int*)g_flag)[b] = 0;
        }
    }
}

extern "C" void kernel_launch(void* const* d_in, const int* in_sizes, int n_in,
                              void* d_out, int out_size)
{
    const float* x = nullptr; const void* mask = nullptr; const void* keep = nullptr;
    const float* bj = nullptr; const float* noise = nullptr; const float* sp = nullptr;

    for (int i = 0; i < n_in; i++) {
        switch (in_sizes[i]) {
            case NB * T_IN * NCC:  x     = (const float*)d_in[i]; break;
            case NB * T_IN:        mask  = d_in[i];               break;
            case NB * NEW_T:       keep  = d_in[i];               break;
            case NB * JF:          bj    = (const float*)d_in[i]; break;
            case NB * NEW_T * NCC: noise = (const float*)d_in[i]; break;
            case NB * NCC:         sp    = (const float*)d_in[i]; break;
            default: break;
        }
    }

    int write_mask = (out_size >= X_ELEMS + NB * NEW_T) ? 1 : 0;
    dim3 grid(XBLOCKS, NB);   // 71 x 32
    fused_kernel<<<grid, BTHREADS>>>(x, noise, sp, mask, keep, bj,
                                     (float*)d_out, write_mask);
}

// round 17
// speedup vs baseline: 1.3524x; 1.3524x over previous
#include <cuda_runtime.h>
#include <math.h>

#define NB      32
#define T_IN    512
#define NEW_T   426
#define NCC     1629            // N*C = 543*3
#define JF      53              // JITTER_FREQ
#define X_ELEMS (NB*NEW_T*NCC)  // 22,205,088
#define BTHREADS 416            // 416*4 = 1664 >= 1629
#define RROWS   6               // 426 = 71 * 6
#define NSTRIPS (NB * (NEW_T / RROWS))  // 2272

// Per-(b,t) table: x = idx0 (or -1.0f if frame kept), y = idx1, z = drop-interp frac, w = jitter
__device__ float4 g_tab[NB * NEW_T];

__device__ __forceinline__ int read_bool(const void* p, int mode, int i) {
    if (mode == 0) return ((const unsigned char*)p)[i] != 0;
    if (mode == 1) return ((const int*)p)[i] != 0;
    return ((const float*)p)[i] != 0.0f;
}

// Warp-shuffle scan setup; all typed keep-loads issued concurrently with probe.
__global__ void setup_kernel(const void* __restrict__ mask,
                             const void* __restrict__ keep,
                             const float* __restrict__ bj,
                             float* __restrict__ out, int write_mask)
{
    __shared__ int   s_wsum[16];
    __shared__ short s_kept[NEW_T];
    __shared__ int   s_K;
    int b = blockIdx.x;
    int t = threadIdx.x;
    int lane = t & 31, warp = t >> 5;

    const int ki = b * NEW_T + t;
    unsigned char probe_u8 = ((const unsigned char*)keep)[NEW_T - 1];
    int           probe_i  = ((const int*)keep)[NEW_T - 1];
    unsigned char kv_u8 = 0; int kv_i = 0; float kv_f = 0.f;
    if (t < NEW_T) {
        kv_u8 = ((const unsigned char*)keep)[ki];
        kv_i  = ((const int*)keep)[ki];
        kv_f  = ((const float*)keep)[ki];
    }
    const int bmode = (probe_u8 != 0) ? 0 : ((probe_i == 1) ? 1 : 2);
    const int kv = (t < NEW_T) ? ((bmode == 0) ? (kv_u8 != 0)
                              :  (bmode == 1) ? (kv_i != 0) : (kv_f != 0.0f)) : 0;

    int v = kv;
    #pragma unroll
    for (int off = 1; off < 32; off <<= 1) {
        int n = __shfl_up_sync(0xffffffffu, v, off);
        if (lane >= off) v += n;
    }
    if (lane == 31) s_wsum[warp] = v;
    __syncthreads();
    if (warp == 0 && lane < 16) {
        int w = s_wsum[lane];
        #pragma unroll
        for (int off = 1; off < 16; off <<= 1) {
            int n = __shfl_up_sync(0xffffu, w, off);
            if (lane >= off) w += n;
        }
        s_wsum[lane] = w;
        if (lane == 13) s_K = w;
    }
    __syncthreads();
    int incl = v + (warp > 0 ? s_wsum[warp - 1] : 0);
    int K = s_K;
    if (t < NEW_T && kv) s_kept[incl - 1] = (short)t;
    __syncthreads();

    if (t < NEW_T) {
        float s  = (float)t * (float)(K - 1) / 425.0f;
        int  r0  = (int)floorf(s);
        if (r0 < 0) r0 = 0;
        if (r0 > K - 2) r0 = K - 2;
        float fr = s - (float)r0;

        float4 tb;
        if (kv) { tb.x = -1.0f; tb.y = 0.0f; tb.z = 0.0f; }
        else    { tb.x = (float)s_kept[r0]; tb.y = (float)s_kept[r0 + 1]; tb.z = fr; }

        float sj = (float)t * (float)(52.0 / 425.0);
        int  j0  = (int)floorf(sj);
        if (j0 > JF - 2) j0 = JF - 2;
        float fj = sj - (float)j0;
        tb.w = (bj[b * JF + j0] * 0.02f) * (1.0f - fj) + (bj[b * JF + j0 + 1] * 0.02f) * fj;

        g_tab[b * NEW_T + t] = tb;
    }

#if __CUDA_ARCH__ >= 900
    cudaTriggerProgrammaticLaunchCompletion();
#endif

    if (t < NEW_T && write_mask) {
        float nf = (float)t * (float)(512.0 / 426.0);
        int ni = (int)floorf(nf);
        if (ni > T_IN - 1) ni = T_IN - 1;
        int m = read_bool(mask, bmode, b * T_IN + ni);
        out[X_ELEMS + b * NEW_T + t] = (m && kv) ? 1.0f : 0.0f;
    }
}

__device__ __forceinline__ void ridx(int tt, int& i0, float& f) {
    float s = (float)tt * (float)(511.0 / 425.0);
    int i = (int)s;
    if (i > T_IN - 2) i = T_IN - 2;
    i0 = i;
    f = s - (float)i;
}

// Compact row metadata: 32-bit element offsets into xb.
struct RowMeta {
    unsigned o0, o1;
    float f0, w0, f1, w1;
    float jit;
    int two;
};

__device__ __forceinline__ RowMeta mkmeta(const float4& tb, int tt, bool zero_jit)
{
    RowMeta m;
    int i0; float f;
    if (tb.x < 0.0f) {
        ridx(tt, i0, f);
        m.o0 = (unsigned)i0 * NCC; m.f0 = f; m.w0 = 1.0f;
        m.two = 0; m.o1 = m.o0; m.f1 = 0.f; m.w1 = 0.f;
    } else {
        ridx((int)tb.x, i0, f);
        m.o0 = (unsigned)i0 * NCC; m.f0 = f; m.w0 = 1.0f - tb.z;
        int i1; float f1; ridx((int)tb.y, i1, f1);
        m.o1 = (unsigned)i1 * NCC; m.f1 = f1; m.w1 = tb.z;
        m.two = 1;
    }
    m.jit = zero_jit ? 0.0f : tb.w;
    return m;
}

__device__ __forceinline__ void issue_arm0(const float* __restrict__ xb, const RowMeta& m,
                                           int tid, float* v0, float* v1)
{
    const float* p = xb + m.o0 + tid;
    #pragma unroll
    for (int k = 0; k < 4; k++) if (tid + k * BTHREADS < NCC) v0[k] = __ldg(p + k * BTHREADS);
    #pragma unroll
    for (int k = 0; k < 4; k++) if (tid + k * BTHREADS < NCC) v1[k] = __ldg(p + NCC + k * BTHREADS);
}

__device__ __forceinline__ void combine(const float* __restrict__ xb, const RowMeta& m,
                                        int tid, const float* v0, const float* v1, float* cur)
{
    #pragma unroll
    for (int k = 0; k < 4; k++)
        cur[k] = m.w0 * (v0[k] * (1.0f - m.f0) + v1[k] * m.f0);
    if (m.two) {                               // block-uniform, rare (~10% rows)
        const float* p = xb + m.o1 + tid;
        float u0[4], u1[4];
        #pragma unroll
        for (int k = 0; k < 4; k++) if (tid + k * BTHREADS < NCC) u0[k] = __ldg(p + k * BTHREADS);
        #pragma unroll
        for (int k = 0; k < 4; k++) if (tid + k * BTHREADS < NCC) u1[k] = __ldg(p + NCC + k * BTHREADS);
        #pragma unroll
        for (int k = 0; k < 4; k++)
            cur[k] += m.w1 * (u0[k] * (1.0f - m.f1) + u1[k] * m.f1);
    }
}

// Persistent main: G = 3*SMs blocks; each loops over strips s = bid, bid+G, ...
// Strip body = R13's 1-deep pipelined 6-row strip. No wave quantization tail.
__global__ void __launch_bounds__(BTHREADS, 3)
main_kernel(const float* __restrict__ x, const float* __restrict__ noise,
            const float* __restrict__ sp, float* __restrict__ out, int nblocks)
{
    const int tid = threadIdx.x;

#if __CUDA_ARCH__ >= 900
    bool synced = false;
#endif

    for (int s = blockIdx.x; s < NSTRIPS; s += nblocks) {
        const int b  = s / (NEW_T / RROWS);
        const int j  = s - b * (NEW_T / RROWS);
        const int t0 = j * RROWS;
        const int row0 = b * NEW_T + t0;

        const float* __restrict__ xb = x + (size_t)b * T_IN * NCC;

        // g_tab-independent loads first (first strip overlaps setup under PDL)
        const float* spp = sp + (size_t)b * NCC + tid;
        float spv[4];
        #pragma unroll
        for (int k = 0; k < 4; k++) if (tid + k * BTHREADS < NCC) spv[k] = __ldg(spp + k * BTHREADS);

        float nz[4];
        {
            const float* np = noise + (size_t)row0 * NCC + tid;
            #pragma unroll
            for (int k = 0; k < 4; k++) if (tid + k * BTHREADS < NCC) nz[k] = __ldcs(np + k * BTHREADS);
        }

#if __CUDA_ARCH__ >= 900
        if (!synced) { cudaGridDependencySynchronize(); synced = true; }
#endif

        // prev = x2(t0-1), unpipelined (once per strip)
        float prev[4] = {0.f, 0.f, 0.f, 0.f};
        if (t0 > 0) {
            RowMeta mp = mkmeta(g_tab[row0 - 1], t0 - 1, false);
            float pv0[4], pv1[4];
            issue_arm0(xb, mp, tid, pv0, pv1);
            combine(xb, mp, tid, pv0, pv1, prev);
        }

        RowMeta mc = mkmeta(g_tab[row0], t0, t0 == 0);
        float va0[4], va1[4];
        issue_arm0(xb, mc, tid, va0, va1);

        #pragma unroll
        for (int i = 0; i < RROWS; i++) {
            const int row = row0 + i;

            RowMeta mn;
            float vb0[4], vb1[4], nz2[4];
            if (i + 1 < RROWS) {
                mn = mkmeta(g_tab[row + 1], t0 + i + 1, false);
                issue_arm0(xb, mn, tid, vb0, vb1);
                const float* np = noise + (size_t)(row + 1) * NCC + tid;
                #pragma unroll
                for (int k = 0; k < 4; k++) if (tid + k * BTHREADS < NCC) nz2[k] = __ldcs(np + k * BTHREADS);
            }

            float cur[4];
            combine(xb, mc, tid, va0, va1, cur);

            float* op = out + (size_t)row * NCC + tid;
            const float jit = mc.jit;
            #pragma unroll
            for (int k = 0; k < 4; k++) {
                if (tid + k * BTHREADS < NCC) {
                    float v = cur[k] + (cur[k] - prev[k]) * jit;   // jit==0 at t==0
                    __stcs(op + k * BTHREADS, v + nz[k] * 0.01f + spv[k] * 0.005f);
                }
            }

            #pragma unroll
            for (int k = 0; k < 4; k++) { prev[k] = cur[k]; va0[k] = vb0[k]; va1[k] = vb1[k]; nz[k] = nz2[k]; }
            mc = mn;
        }
    }
}

extern "C" void kernel_launch(void* const* d_in, const int* in_sizes, int n_in,
                              void* d_out, int out_size)
{
    const float* x = nullptr; const void* mask = nullptr; const void* keep = nullptr;
    const float* bj = nullptr; const float* noise = nullptr; const float* sp = nullptr;

    for (int i = 0; i < n_in; i++) {
        switch (in_sizes[i]) {
            case NB * T_IN * NCC:  x     = (const float*)d_in[i]; break;
            case NB * T_IN:        mask  = d_in[i];               break;
            case NB * NEW_T:       keep  = d_in[i];               break;
            case NB * JF:          bj    = (const float*)d_in[i]; break;
            case NB * NEW_T * NCC: noise = (const float*)d_in[i]; break;
            case NB * NCC:         sp    = (const float*)d_in[i]; break;
            default: break;
        }
    }

    int write_mask = (out_size >= X_ELEMS + NB * NEW_T) ? 1 : 0;
    setup_kernel<<<NB, 512>>>(mask, keep, bj, (float*)d_out, write_mask);

    int nsm = 148;
    cudaDeviceProp prop;
    if (cudaGetDeviceProperties(&prop, 0) == cudaSuccess) nsm = prop.multiProcessorCount;
    int G = nsm * 3;
    if (G > NSTRIPS) G = NSTRIPS;

    float* outp = (float*)d_out;

    // PDL launch of main; fall back to a plain launch if unsupported.
    cudaLaunchConfig_t cfg = {};
    cfg.gridDim = dim3((unsigned)G, 1, 1);
    cfg.blockDim = dim3(BTHREADS, 1, 1);
    cfg.dynamicSmemBytes = 0;
    cfg.stream = 0;
    cudaLaunchAttribute attrs[1];
    attrs[0].id = cudaLaunchAttributeProgrammaticStreamSerialization;
    attrs[0].val.programmaticStreamSerializationAllowed = 1;
    cfg.attrs = attrs;
    cfg.numAttrs = 1;

    cudaError_t err = cudaLaunchKernelEx(&cfg, main_kernel, x, noise, sp, outp, G);
    if (err != cudaSuccess) {
        (void)cudaGetLastError();   // clear sticky error, launch normally
        main_kernel<<<G, BTHREADS>>>(x, noise, sp, outp, G);
    }
}